// round 15
// baseline (speedup 1.0000x reference)
#include <cuda_runtime.h>
#include <cuda_fp16.h>
#include <math.h>
#include <stdint.h>

#define N_NODES 3000
#define NROW_P  3008
#define IN_DIM  512
#define HID     64
#define HEADS   8
#define CAT     512
#define NCLASS  16
#define MAXDEG  256
#define PDEG    260
#define ALPHA   0.2f
#define NCHUNK  16        // IN_DIM/32

// ---------------- scratch -----------------------------------------------------
__device__ float    g_dinv[N_NODES];
__device__ float    g_dsc [N_NODES];
__device__ int      g_cnt [N_NODES];
__device__ int      g_cols[N_NODES * MAXDEG];
__device__ uint32_t g_At  [NCHUNK * NROW_P * 32];       // tf32 A, k-interleaved
__device__ uint32_t g_WcT [HEADS * NCHUNK * 64 * 32];   // tf32 W, transposed+interleaved
__device__ __half   g_Hh  [N_NODES * CAT];              // fp16 h for attn1 gather
__device__ float    g_srcT[N_NODES * HEADS];
__device__ float    g_dstT[N_NODES * HEADS];
__device__ float    g_X1  [N_NODES * CAT];
__device__ float    g_H2  [N_NODES * NCLASS];
__device__ float    g_s2  [N_NODES];
__device__ float    g_d2  [N_NODES];

__device__ __forceinline__ float elu1(float x) { return x > 0.f ? x : expm1f(x); }
__device__ __forceinline__ float lrelu(float x){ return x >= 0.f ? x : ALPHA * x; }
__device__ __forceinline__ uint32_t f2tf32(float f) {
    uint32_t u; asm("cvt.rna.tf32.f32 %0, %1;" : "=r"(u) : "f"(f)); return u;
}
__device__ __forceinline__ void mma_tf32(float* c, const uint32_t* a, const uint32_t* b) {
    asm volatile(
        "mma.sync.aligned.m16n8k8.row.col.f32.tf32.tf32.f32 "
        "{%0,%1,%2,%3}, {%4,%5,%6,%7}, {%8,%9}, {%0,%1,%2,%3};\n"
        : "+f"(c[0]), "+f"(c[1]), "+f"(c[2]), "+f"(c[3])
        : "r"(a[0]), "r"(a[1]), "r"(a[2]), "r"(a[3]), "r"(b[0]), "r"(b[1]));
}

// ---------------- 1. fused prep: pack_w (blocks 0..127) + prep_A (rest) ------
__global__ __launch_bounds__(256) void prep_all(const float* __restrict__ W_heads,
                                                const float* __restrict__ feat) {
    int b = blockIdx.x;
    int t = threadIdx.x;
    if (b < HEADS * NCHUNK) {
        int h = b >> 4, ch = b & 15;
#pragma unroll
        for (int i = 0; i < 8; i++) {
            int idx = t * 8 + i;
            int n = idx >> 5, c = idx & 31;
            int kl = (c & 7) * 4 + (c >> 3);
            float v = W_heads[((size_t)h * IN_DIM + ch * 32 + kl) * HID + n];
            g_WcT[(((size_t)h * NCHUNK + ch) * 64 + n) * 32 + c] = f2tf32(v);
        }
    } else {
        int row = b - HEADS * NCHUNK;
        int k = t * 2;
        int ch = k >> 5, kl = k & 31;
        float2 v = *(const float2*)(feat + (size_t)row * IN_DIM + k);
        uint32_t* dst = g_At + ((size_t)ch * NROW_P + row) * 32;
        int c0 = (kl & 3) * 8 + (kl >> 2);
        dst[c0]     = f2tf32(v.x);
        dst[c0 + 8] = f2tf32(v.y);
    }
}

// ---------------- 2. tf32 GEMM + fused src/dst epilogue ----------------------
#define LDI 36
__global__ __launch_bounds__(128) void sgemm_tc(const float* __restrict__ a_heads) {
    __shared__ uint32_t As[2][64 * LDI];
    __shared__ uint32_t Bs[2][64 * LDI];
    __shared__ float s_src[64][2];
    __shared__ float s_dst[64][2];

    int tid = threadIdx.x;
    int warp = tid >> 5, lane = tid & 31;
    int warp_m = warp & 1, warp_n = warp >> 1;
    int gid = lane >> 2, tig = lane & 3;
    int head = blockIdx.x;
    int brow = blockIdx.y * 64;
    int bcol = head * 64;

    int srow = tid >> 3, scol = (tid & 7) * 4;
    const uint32_t* Asrc = g_At + (size_t)brow * 32;
    const uint32_t* Bsrc = g_WcT + (size_t)head * NCHUNK * 64 * 32;

    uint4 va[4], vb[4];
#pragma unroll
    for (int i = 0; i < 4; i++) {
        va[i] = *(const uint4*)(Asrc + (size_t)tid * 4 + i * 512);
        vb[i] = *(const uint4*)(Bsrc + (size_t)tid * 4 + i * 512);
    }
#pragma unroll
    for (int i = 0; i < 4; i++) {
        *(uint4*)&As[0][(srow + i * 16) * LDI + scol] = va[i];
        *(uint4*)&Bs[0][(srow + i * 16) * LDI + scol] = vb[i];
    }
    __syncthreads();

    float c[2][4][4] = {};
    int cur = 0;
    for (int ch = 0; ch < NCHUNK; ch++) {
        bool last = (ch == NCHUNK - 1);
        if (!last) {
            const uint32_t* An = Asrc + (size_t)(ch + 1) * NROW_P * 32;
            const uint32_t* Bn = Bsrc + (size_t)(ch + 1) * 2048;
#pragma unroll
            for (int i = 0; i < 4; i++) {
                va[i] = *(const uint4*)(An + (size_t)tid * 4 + i * 512);
                vb[i] = *(const uint4*)(Bn + (size_t)tid * 4 + i * 512);
            }
        }
        uint32_t alo[2][8], ahi[2][8], bf[4][8];
#pragma unroll
        for (int mt = 0; mt < 2; mt++) {
            int rowA = warp_m * 32 + mt * 16 + gid;
            *(uint4*)&alo[mt][0] = *(uint4*)&As[cur][rowA * LDI + tig * 8];
            *(uint4*)&alo[mt][4] = *(uint4*)&As[cur][rowA * LDI + tig * 8 + 4];
            *(uint4*)&ahi[mt][0] = *(uint4*)&As[cur][(rowA + 8) * LDI + tig * 8];
            *(uint4*)&ahi[mt][4] = *(uint4*)&As[cur][(rowA + 8) * LDI + tig * 8 + 4];
        }
#pragma unroll
        for (int nt = 0; nt < 4; nt++) {
            int rowB = warp_n * 32 + nt * 8 + gid;
            *(uint4*)&bf[nt][0] = *(uint4*)&Bs[cur][rowB * LDI + tig * 8];
            *(uint4*)&bf[nt][4] = *(uint4*)&Bs[cur][rowB * LDI + tig * 8 + 4];
        }
#pragma unroll
        for (int ks = 0; ks < 4; ks++) {
#pragma unroll
            for (int mt = 0; mt < 2; mt++) {
                uint32_t a[4] = {alo[mt][2 * ks], ahi[mt][2 * ks],
                                 alo[mt][2 * ks + 1], ahi[mt][2 * ks + 1]};
#pragma unroll
                for (int nt = 0; nt < 4; nt++) {
                    uint32_t b[2] = {bf[nt][2 * ks], bf[nt][2 * ks + 1]};
                    mma_tf32(c[mt][nt], a, b);
                }
            }
        }
        if (!last) {
            int nxt = cur ^ 1;
#pragma unroll
            for (int i = 0; i < 4; i++) {
                *(uint4*)&As[nxt][(srow + i * 16) * LDI + scol] = va[i];
                *(uint4*)&Bs[nxt][(srow + i * 16) * LDI + scol] = vb[i];
            }
        }
        __syncthreads();
        cur ^= 1;
    }

    const float* av = a_heads + head * (2 * HID);
    float ps[2][2] = {}, pd[2][2] = {};
#pragma unroll
    for (int mt = 0; mt < 2; mt++) {
        int row0 = brow + warp_m * 32 + mt * 16 + gid;
#pragma unroll
        for (int nt = 0; nt < 4; nt++) {
            int cl = warp_n * 32 + nt * 8 + 2 * tig;
            float c0 = c[mt][nt][0], c1 = c[mt][nt][1];
            float c2 = c[mt][nt][2], c3 = c[mt][nt][3];
            float as0 = av[cl], as1 = av[cl + 1];
            float ad0 = av[64 + cl], ad1 = av[64 + cl + 1];
            ps[mt][0] += c0 * as0 + c1 * as1;
            pd[mt][0] += c0 * ad0 + c1 * ad1;
            ps[mt][1] += c2 * as0 + c3 * as1;
            pd[mt][1] += c2 * ad0 + c3 * ad1;
            int colg = bcol + cl;
            if (row0 < N_NODES)
                *(__half2*)(g_Hh + (size_t)row0 * CAT + colg) = __floats2half2_rn(c0, c1);
            if (row0 + 8 < N_NODES)
                *(__half2*)(g_Hh + (size_t)(row0 + 8) * CAT + colg) = __floats2half2_rn(c2, c3);
        }
    }
#pragma unroll
    for (int mt = 0; mt < 2; mt++)
#pragma unroll
        for (int h = 0; h < 2; h++) {
            ps[mt][h] += __shfl_xor_sync(0xffffffffu, ps[mt][h], 1);
            ps[mt][h] += __shfl_xor_sync(0xffffffffu, ps[mt][h], 2);
            pd[mt][h] += __shfl_xor_sync(0xffffffffu, pd[mt][h], 1);
            pd[mt][h] += __shfl_xor_sync(0xffffffffu, pd[mt][h], 2);
        }
    if (tig == 0) {
#pragma unroll
        for (int mt = 0; mt < 2; mt++)
#pragma unroll
            for (int h = 0; h < 2; h++) {
                int rl = warp_m * 32 + mt * 16 + gid + 8 * h;
                s_src[rl][warp_n] = ps[mt][h];
                s_dst[rl][warp_n] = pd[mt][h];
            }
    }
    __syncthreads();
    {
        int rl = tid >> 1, which = tid & 1;
        int row = brow + rl;
        if (row < N_NODES) {
            if (which == 0) g_srcT[row * HEADS + head] = s_src[rl][0] + s_src[rl][1];
            else            g_dstT[row * HEADS + head] = s_dst[rl][0] + s_dst[rl][1];
        }
    }
}

// ---------------- 3. edge build (indices only; binary adjacency) -------------
#define SEGQ 188
__global__ __launch_bounds__(128) void build_edges(const float* __restrict__ adj) {
    int row  = blockIdx.x;
    int tid  = threadIdx.x;
    int w    = tid >> 5, lane = tid & 31;
    __shared__ int   s_bufc[4][128];
    __shared__ int   s_cnt[4];
    __shared__ float s_diag;

    const float4* arow4 = (const float4*)(adj + (size_t)row * N_NODES);
    const int NQ = N_NODES / 4;
    int q0 = w * SEGQ;
    int q1 = min(q0 + SEGQ, NQ);

    int cnt = 0;
    for (int base = q0; base < q1; base += 32) {
        int q = base + lane;
        bool valid = q < q1;
        float a[4] = {0.f, 0.f, 0.f, 0.f};
        int j0 = q * 4;
        if (valid) {
            float4 v = arow4[q];
            a[0] = v.x; a[1] = v.y; a[2] = v.z; a[3] = v.w;
            if (row >= j0 && row < j0 + 4) {
                a[row - j0] += 1.f;
                s_diag = a[row - j0];
            }
        }
#pragma unroll
        for (int t = 0; t < 4; t++) {
            bool has = valid && (a[t] > 0.f);
            unsigned msk = __ballot_sync(0xffffffffu, has);
            if (has) {
                int pos = cnt + __popc(msk & ((1u << lane) - 1u));
                if (pos < 128) s_bufc[w][pos] = j0 + t;
            }
            cnt += __popc(msk);
        }
    }
    if (lane == 0) s_cnt[w] = cnt;
    __syncthreads();

    int c0 = 0;
#pragma unroll
    for (int t = 0; t < 4; t++) if (t < w) c0 += s_cnt[t];
    int myc = min(s_cnt[w], 128);
    for (int k = lane; k < myc; k += 32) {
        int pos = c0 + k;
        if (pos < MAXDEG) g_cols[row * MAXDEG + pos] = s_bufc[w][k];
    }
    if (tid == 0) {
        int tot = s_cnt[0] + s_cnt[1] + s_cnt[2] + s_cnt[3];
        float dsc = s_diag;
        g_cnt[row]  = tot < MAXDEG ? tot : MAXDEG;
        g_dinv[row] = rsqrtf((float)tot + dsc - 1.f);
        g_dsc[row]  = dsc;
    }
}

// ---------------- 4. layer-1 attention: packed (coef,col) + HFMA2 gather -----
__global__ __launch_bounds__(256, 8) void attn1() {
    int i = blockIdx.x;
    int tid = threadIdx.x;
    int head = tid >> 5, lane = tid & 31;
    __shared__ int    s_colstage[MAXDEG];       // j * 1024 bytes
    __shared__ float  s_w[MAXDEG];
    __shared__ float2 s_pc[HEADS][PDEG];        // .x = e/prob/coefbits, .y = colbytes
    __shared__ float  s_si[HEADS];
    int n = g_cnt[i];
    int n8 = (n + 7) & ~7;
    float di = g_dinv[i];
    float dsc = g_dsc[i];
    for (int k = tid; k < n8; k += 256) {
        if (k < n) {
            int j = g_cols[i * MAXDEG + k];
            s_colstage[k] = j << 10;
            float wv = di * g_dinv[j];
            s_w[k] = (j == i) ? wv * dsc : wv;
        } else {
            s_colstage[k] = 0;
        }
    }
    if (tid < HEADS) s_si[tid] = g_srcT[i * HEADS + tid];
    __syncthreads();

    // phase 1: cooperative e-matrix; replicate col into packed per-head array
    {
        int eh_e = tid >> 3, eh_h = tid & 7;
        float si_h = s_si[eh_h];
        for (int k = eh_e; k < n8; k += 32) {
            int colb = s_colstage[k];
            float ev = 0.f;
            if (k < n) {
                float dst = __ldg(g_dstT + (colb >> 7) + eh_h);   // j*8 + h
                ev = lrelu(si_h + dst);
            }
            s_pc[eh_h][k] = make_float2(ev, __int_as_float(colb));
        }
    }
    __syncthreads();

    // phase 2: per-head softmax; finalize coef as packed half2 (in .x)
    float m = -1e30f;
    for (int k = lane; k < n; k += 32) m = fmaxf(m, s_pc[head][k].x);
#pragma unroll
    for (int o = 16; o; o >>= 1) m = fmaxf(m, __shfl_xor_sync(0xffffffffu, m, o));
    float s = 0.f;
    for (int k = lane; k < n; k += 32) {
        float p = __expf(s_pc[head][k].x - m);
        s_pc[head][k].x = p;
        s += p;
    }
#pragma unroll
    for (int o = 16; o; o >>= 1) s += __shfl_xor_sync(0xffffffffu, s, o);
    float inv = 1.f / s;
    for (int k = lane; k < n8; k += 32) {
        float c = (k < n) ? s_pc[head][k].x * inv * s_w[k] : 0.f;
        __half2 c2 = __float2half2_rn(c);
        s_pc[head][k].x = __uint_as_float(*(uint32_t*)&c2);
    }
    __syncwarp();

    // phase 3: HFMA2 gather; lane = (e,f); dual accumulators for ILP
    int e = lane >> 3, f = lane & 7;
    const char* Hbase = (const char*)(g_Hh + head * HID + f * 8);
    float accf[8] = {};
    const __half2 z2 = __float2half2_rn(0.f);
    for (int k = 0; k < n8; k += 8) {
        float2 pc0 = s_pc[head][k + e];
        float2 pc1 = s_pc[head][k + 4 + e];
        uint32_t cb0 = __float_as_uint(pc0.x), cb1 = __float_as_uint(pc1.x);
        __half2 c20 = *reinterpret_cast<__half2*>(&cb0);
        __half2 c21 = *reinterpret_cast<__half2*>(&cb1);
        uint4 r0 = *(const uint4*)(Hbase + __float_as_int(pc0.y));
        uint4 r1 = *(const uint4*)(Hbase + __float_as_int(pc1.y));
        const __half2* h0 = (const __half2*)&r0;
        const __half2* h1 = (const __half2*)&r1;
        __half2 ha0 = __hmul2(c20, h0[0]), ha1 = __hmul2(c20, h0[1]);
        __half2 ha2 = __hmul2(c20, h0[2]), ha3 = __hmul2(c20, h0[3]);
        __half2 hb0 = __hmul2(c21, h1[0]), hb1 = __hmul2(c21, h1[1]);
        __half2 hb2 = __hmul2(c21, h1[2]), hb3 = __hmul2(c21, h1[3]);
        ha0 = __hadd2(ha0, hb0); ha1 = __hadd2(ha1, hb1);
        ha2 = __hadd2(ha2, hb2); ha3 = __hadd2(ha3, hb3);
        float2 f0 = __half22float2(ha0), f1 = __half22float2(ha1);
        float2 f2 = __half22float2(ha2), f3 = __half22float2(ha3);
        accf[0] += f0.x; accf[1] += f0.y; accf[2] += f1.x; accf[3] += f1.y;
        accf[4] += f2.x; accf[5] += f2.y; accf[6] += f3.x; accf[7] += f3.y;
    }
#pragma unroll
    for (int t = 0; t < 8; t++) {
        accf[t] += __shfl_xor_sync(0xffffffffu, accf[t], 8);
        accf[t] += __shfl_xor_sync(0xffffffffu, accf[t], 16);
    }
    if (e == 0) {
        float4 o0 = make_float4(elu1(accf[0]), elu1(accf[1]), elu1(accf[2]), elu1(accf[3]));
        float4 o1 = make_float4(elu1(accf[4]), elu1(accf[5]), elu1(accf[6]), elu1(accf[7]));
        float* dst = g_X1 + (size_t)i * CAT + head * HID + f * 8;
        *(float4*)(dst)     = o0;
        *(float4*)(dst + 4) = o1;
    }
}

// ---------------- 5. H2 + src2/dst2: 4 rows/block, W_out in smem -------------
__global__ __launch_bounds__(256) void h2_srcdst(const float* __restrict__ W_out,
                                                 const float* __restrict__ a_out) {
    int i0 = blockIdx.x * 4;
    int tid = threadIdx.x;
    __shared__ float sW[IN_DIM * NCLASS];      // 32KB
    __shared__ float sx[4][IN_DIM];            // 8KB
    __shared__ float sp[4][2][NCLASS];
    __shared__ float sh[4][NCLASS];
#pragma unroll
    for (int q = 0; q < 8; q++)
        *(float4*)&sW[tid * 4 + q * 1024] = *(const float4*)(W_out + tid * 4 + q * 1024);
#pragma unroll
    for (int q = 0; q < 2; q++) {
        int idx = tid * 4 + q * 1024;
        *(float4*)&sx[idx >> 9][idx & 511] = *(const float4*)(g_X1 + (size_t)i0 * IN_DIM + idx);
    }
    __syncthreads();

    int warp = tid >> 5, lane = tid & 31;
    int r = warp >> 1, half = warp & 1;
    int c = lane & 15, sub = lane >> 4;
    float p = 0.f;
    int kbase = half * 256;
#pragma unroll 8
    for (int kk = 0; kk < 128; kk++) {
        int k = kbase + kk * 2 + sub;
        p = fmaf(sx[r][k], sW[k * NCLASS + c], p);
    }
    p += __shfl_xor_sync(0xffffffffu, p, 16);
    if (sub == 0) sp[r][half][c] = p;
    __syncthreads();
    if (tid < 64) {
        int rr = tid >> 4, cc = tid & 15;
        float v = sp[rr][0][cc] + sp[rr][1][cc];
        g_H2[(i0 + rr) * NCLASS + cc] = v;
        sh[rr][cc] = v;
    }
    __syncthreads();
    if (tid < 8) {
        int rr = tid >> 1, which = tid & 1;
        const float* a = a_out + which * NCLASS;
        float v = 0.f;
#pragma unroll
        for (int cc = 0; cc < NCLASS; cc++) v = fmaf(sh[rr][cc], __ldg(a + cc), v);
        if (which == 0) g_s2[i0 + rr] = v;
        else            g_d2[i0 + rr] = v;
    }
}

// ---------------- 6. fused layer-2 attention + FC head + log_softmax ---------
__global__ void attn2_head(const float* __restrict__ FC1,
                           const float* __restrict__ FC2,
                           float* __restrict__ out) {
    int w = threadIdx.x >> 5, lane = threadIdx.x & 31;
    int i = blockIdx.x * 4 + w;
    __shared__ int   s_c[4][MAXDEG];
    __shared__ float s_w[4][MAXDEG];
    __shared__ float s_p[4][MAXDEG];
    if (i >= N_NODES) return;
    int n = g_cnt[i];
    float si = g_s2[i];
    float di = g_dinv[i];
    float dsc = g_dsc[i];
    float m = -1e30f;
    for (int k = lane; k < n; k += 32) {
        int j = g_cols[i * MAXDEG + k];
        s_c[w][k] = j;
        float wv = di * g_dinv[j];
        s_w[w][k] = (j == i) ? wv * dsc : wv;
        float e = lrelu(si + g_d2[j]);
        s_p[w][k] = e;
        m = fmaxf(m, e);
    }
#pragma unroll
    for (int o = 16; o; o >>= 1) m = fmaxf(m, __shfl_xor_sync(0xffffffffu, m, o));
    float s = 0.f;
    for (int k = lane; k < n; k += 32) {
        float p = __expf(s_p[w][k] - m);
        s_p[w][k] = p;
        s += p;
    }
#pragma unroll
    for (int o = 16; o; o >>= 1) s += __shfl_xor_sync(0xffffffffu, s, o);
    float inv = 1.f / s;
    __syncwarp();
    float z = 0.f;
    if (lane < NCLASS) {
        float acc = 0.f;
        for (int k = 0; k < n; k++) {
            float coef = s_p[w][k] * inv * s_w[w][k];
            acc = fmaf(coef, g_H2[s_c[w][k] * NCLASS + lane], acc);
        }
        z = elu1(elu1(acc));
    }
    // FC head (warp-level, z on lanes 0..15)
    float y1 = 0.f;
#pragma unroll
    for (int k = 0; k < NCLASS; k++) {
        float zk = __shfl_sync(0xffffffffu, z, k);
        if (lane < NCLASS) y1 = fmaf(zk, __ldg(FC1 + lane * NCLASS + k), y1);
    }
    y1 = elu1(y1);
    float y2 = 0.f;
#pragma unroll
    for (int k = 0; k < NCLASS; k++) {
        float yk = __shfl_sync(0xffffffffu, y1, k);
        if (lane < NCLASS) y2 = fmaf(yk, __ldg(FC2 + lane * NCLASS + k), y2);
    }
    y2 = elu1(y2);
    float v = (lane < NCLASS) ? y2 : -1e30f;
#pragma unroll
    for (int o = 8; o; o >>= 1) v = fmaxf(v, __shfl_xor_sync(0xffffffffu, v, o));
    float e = (lane < NCLASS) ? expf(y2 - v) : 0.f;
    float sum = e;
#pragma unroll
    for (int o = 8; o; o >>= 1) sum += __shfl_xor_sync(0xffffffffu, sum, o);
    if (lane < NCLASS) out[i * NCLASS + lane] = y2 - v - logf(sum);
}

// ---------------- launcher ---------------------------------------------------
extern "C" void kernel_launch(void* const* d_in, const int* in_sizes, int n_in,
                              void* d_out, int out_size) {
    const float* adj     = (const float*)d_in[0];
    const float* feat    = (const float*)d_in[1];
    const float* W_heads = (const float*)d_in[2];
    const float* a_heads = (const float*)d_in[3];
    const float* W_out   = (const float*)d_in[4];
    const float* a_out   = (const float*)d_in[5];
    const float* FC1     = (const float*)d_in[6];
    const float* FC2     = (const float*)d_in[7];
    float* out = (float*)d_out;

    prep_all   <<<HEADS * NCHUNK + N_NODES, 256>>>(W_heads, feat);       // 1
    sgemm_tc   <<<dim3(HEADS, (N_NODES + 63) / 64), 128>>>(a_heads);     // 2
    build_edges<<<N_NODES, 128>>>(adj);                                  // 3
    attn1      <<<N_NODES, 256>>>();                                     // 4 (profiled)
    h2_srcdst  <<<N_NODES / 4, 256>>>(W_out, a_out);                     // 5
    attn2_head <<<(N_NODES + 3) / 4, 128>>>(FC1, FC2, out);              // 6
}

// round 16
// speedup vs baseline: 1.1428x; 1.1428x over previous
#include <cuda_runtime.h>
#include <cuda_fp16.h>
#include <math.h>
#include <stdint.h>

#define N_NODES 3000
#define NROW_P  3008
#define IN_DIM  512
#define HID     64
#define HEADS   8
#define CAT     512
#define NCLASS  16
#define MAXDEG  256
#define PDEG    260
#define ALPHA   0.2f
#define NCHUNK  16        // IN_DIM/32

// ---------------- scratch -----------------------------------------------------
__device__ float    g_dinv[N_NODES];
__device__ float    g_dsc [N_NODES];
__device__ int      g_cnt [N_NODES];
__device__ int      g_cols[N_NODES * MAXDEG];
__device__ uint32_t g_At  [NCHUNK * NROW_P * 32];       // tf32 A, k-interleaved
__device__ uint32_t g_WcT [HEADS * NCHUNK * 64 * 32];   // tf32 W, transposed+interleaved
__device__ __half   g_Hh  [N_NODES * CAT];              // fp16 h for attn1 gather
__device__ float    g_srcT[N_NODES * HEADS];
__device__ float    g_dstT[N_NODES * HEADS];
__device__ float    g_X1  [N_NODES * CAT];
__device__ float    g_H2  [N_NODES * NCLASS];
__device__ float    g_s2  [N_NODES];
__device__ float    g_d2  [N_NODES];

__device__ __forceinline__ float elu1(float x) { return x > 0.f ? x : expm1f(x); }
__device__ __forceinline__ float lrelu(float x){ return x >= 0.f ? x : ALPHA * x; }
__device__ __forceinline__ uint32_t f2tf32(float f) {
    uint32_t u; asm("cvt.rna.tf32.f32 %0, %1;" : "=r"(u) : "f"(f)); return u;
}
__device__ __forceinline__ void mma_tf32(float* c, const uint32_t* a, const uint32_t* b) {
    asm volatile(
        "mma.sync.aligned.m16n8k8.row.col.f32.tf32.tf32.f32 "
        "{%0,%1,%2,%3}, {%4,%5,%6,%7}, {%8,%9}, {%0,%1,%2,%3};\n"
        : "+f"(c[0]), "+f"(c[1]), "+f"(c[2]), "+f"(c[3])
        : "r"(a[0]), "r"(a[1]), "r"(a[2]), "r"(a[3]), "r"(b[0]), "r"(b[1]));
}

// ---------------- 1. fused prep: pack_w (blocks 0..127) + prep_A (rest) ------
__global__ __launch_bounds__(256) void prep_all(const float* __restrict__ W_heads,
                                                const float* __restrict__ feat) {
    int b = blockIdx.x;
    int t = threadIdx.x;
    if (b < HEADS * NCHUNK) {
        int h = b >> 4, ch = b & 15;
#pragma unroll
        for (int i = 0; i < 8; i++) {
            int idx = t * 8 + i;
            int n = idx >> 5, c = idx & 31;
            int kl = (c & 7) * 4 + (c >> 3);
            float v = W_heads[((size_t)h * IN_DIM + ch * 32 + kl) * HID + n];
            g_WcT[(((size_t)h * NCHUNK + ch) * 64 + n) * 32 + c] = f2tf32(v);
        }
    } else {
        int row = b - HEADS * NCHUNK;
        int k = t * 2;
        int ch = k >> 5, kl = k & 31;
        float2 v = *(const float2*)(feat + (size_t)row * IN_DIM + k);
        uint32_t* dst = g_At + ((size_t)ch * NROW_P + row) * 32;
        int c0 = (kl & 3) * 8 + (kl >> 2);
        dst[c0]     = f2tf32(v.x);
        dst[c0 + 8] = f2tf32(v.y);
    }
}

// ---------------- 2. tf32 GEMM + fused src/dst epilogue ----------------------
#define LDI 36
__global__ __launch_bounds__(128) void sgemm_tc(const float* __restrict__ a_heads) {
    __shared__ uint32_t As[2][64 * LDI];
    __shared__ uint32_t Bs[2][64 * LDI];
    __shared__ float s_src[64][2];
    __shared__ float s_dst[64][2];

    int tid = threadIdx.x;
    int warp = tid >> 5, lane = tid & 31;
    int warp_m = warp & 1, warp_n = warp >> 1;
    int gid = lane >> 2, tig = lane & 3;
    int head = blockIdx.x;
    int brow = blockIdx.y * 64;
    int bcol = head * 64;

    int srow = tid >> 3, scol = (tid & 7) * 4;
    const uint32_t* Asrc = g_At + (size_t)brow * 32;
    const uint32_t* Bsrc = g_WcT + (size_t)head * NCHUNK * 64 * 32;

    uint4 va[4], vb[4];
#pragma unroll
    for (int i = 0; i < 4; i++) {
        va[i] = *(const uint4*)(Asrc + (size_t)tid * 4 + i * 512);
        vb[i] = *(const uint4*)(Bsrc + (size_t)tid * 4 + i * 512);
    }
#pragma unroll
    for (int i = 0; i < 4; i++) {
        *(uint4*)&As[0][(srow + i * 16) * LDI + scol] = va[i];
        *(uint4*)&Bs[0][(srow + i * 16) * LDI + scol] = vb[i];
    }
    __syncthreads();

    float c[2][4][4] = {};
    int cur = 0;
    for (int ch = 0; ch < NCHUNK; ch++) {
        bool last = (ch == NCHUNK - 1);
        if (!last) {
            const uint32_t* An = Asrc + (size_t)(ch + 1) * NROW_P * 32;
            const uint32_t* Bn = Bsrc + (size_t)(ch + 1) * 2048;
#pragma unroll
            for (int i = 0; i < 4; i++) {
                va[i] = *(const uint4*)(An + (size_t)tid * 4 + i * 512);
                vb[i] = *(const uint4*)(Bn + (size_t)tid * 4 + i * 512);
            }
        }
        uint32_t alo[2][8], ahi[2][8], bf[4][8];
#pragma unroll
        for (int mt = 0; mt < 2; mt++) {
            int rowA = warp_m * 32 + mt * 16 + gid;
            *(uint4*)&alo[mt][0] = *(uint4*)&As[cur][rowA * LDI + tig * 8];
            *(uint4*)&alo[mt][4] = *(uint4*)&As[cur][rowA * LDI + tig * 8 + 4];
            *(uint4*)&ahi[mt][0] = *(uint4*)&As[cur][(rowA + 8) * LDI + tig * 8];
            *(uint4*)&ahi[mt][4] = *(uint4*)&As[cur][(rowA + 8) * LDI + tig * 8 + 4];
        }
#pragma unroll
        for (int nt = 0; nt < 4; nt++) {
            int rowB = warp_n * 32 + nt * 8 + gid;
            *(uint4*)&bf[nt][0] = *(uint4*)&Bs[cur][rowB * LDI + tig * 8];
            *(uint4*)&bf[nt][4] = *(uint4*)&Bs[cur][rowB * LDI + tig * 8 + 4];
        }
#pragma unroll
        for (int ks = 0; ks < 4; ks++) {
#pragma unroll
            for (int mt = 0; mt < 2; mt++) {
                uint32_t a[4] = {alo[mt][2 * ks], ahi[mt][2 * ks],
                                 alo[mt][2 * ks + 1], ahi[mt][2 * ks + 1]};
#pragma unroll
                for (int nt = 0; nt < 4; nt++) {
                    uint32_t b[2] = {bf[nt][2 * ks], bf[nt][2 * ks + 1]};
                    mma_tf32(c[mt][nt], a, b);
                }
            }
        }
        if (!last) {
            int nxt = cur ^ 1;
#pragma unroll
            for (int i = 0; i < 4; i++) {
                *(uint4*)&As[nxt][(srow + i * 16) * LDI + scol] = va[i];
                *(uint4*)&Bs[nxt][(srow + i * 16) * LDI + scol] = vb[i];
            }
        }
        __syncthreads();
        cur ^= 1;
    }

    const float* av = a_heads + head * (2 * HID);
    float ps[2][2] = {}, pd[2][2] = {};
#pragma unroll
    for (int mt = 0; mt < 2; mt++) {
        int row0 = brow + warp_m * 32 + mt * 16 + gid;
#pragma unroll
        for (int nt = 0; nt < 4; nt++) {
            int cl = warp_n * 32 + nt * 8 + 2 * tig;
            float c0 = c[mt][nt][0], c1 = c[mt][nt][1];
            float c2 = c[mt][nt][2], c3 = c[mt][nt][3];
            float as0 = av[cl], as1 = av[cl + 1];
            float ad0 = av[64 + cl], ad1 = av[64 + cl + 1];
            ps[mt][0] += c0 * as0 + c1 * as1;
            pd[mt][0] += c0 * ad0 + c1 * ad1;
            ps[mt][1] += c2 * as0 + c3 * as1;
            pd[mt][1] += c2 * ad0 + c3 * ad1;
            int colg = bcol + cl;
            if (row0 < N_NODES)
                *(__half2*)(g_Hh + (size_t)row0 * CAT + colg) = __floats2half2_rn(c0, c1);
            if (row0 + 8 < N_NODES)
                *(__half2*)(g_Hh + (size_t)(row0 + 8) * CAT + colg) = __floats2half2_rn(c2, c3);
        }
    }
#pragma unroll
    for (int mt = 0; mt < 2; mt++)
#pragma unroll
        for (int h = 0; h < 2; h++) {
            ps[mt][h] += __shfl_xor_sync(0xffffffffu, ps[mt][h], 1);
            ps[mt][h] += __shfl_xor_sync(0xffffffffu, ps[mt][h], 2);
            pd[mt][h] += __shfl_xor_sync(0xffffffffu, pd[mt][h], 1);
            pd[mt][h] += __shfl_xor_sync(0xffffffffu, pd[mt][h], 2);
        }
    if (tig == 0) {
#pragma unroll
        for (int mt = 0; mt < 2; mt++)
#pragma unroll
            for (int h = 0; h < 2; h++) {
                int rl = warp_m * 32 + mt * 16 + gid + 8 * h;
                s_src[rl][warp_n] = ps[mt][h];
                s_dst[rl][warp_n] = pd[mt][h];
            }
    }
    __syncthreads();
    {
        int rl = tid >> 1, which = tid & 1;
        int row = brow + rl;
        if (row < N_NODES) {
            if (which == 0) g_srcT[row * HEADS + head] = s_src[rl][0] + s_src[rl][1];
            else            g_dstT[row * HEADS + head] = s_dst[rl][0] + s_dst[rl][1];
        }
    }
}

// ---------------- 3. edge build (indices only; binary adjacency) -------------
#define SEGQ 188
__global__ __launch_bounds__(128) void build_edges(const float* __restrict__ adj) {
    int row  = blockIdx.x;
    int tid  = threadIdx.x;
    int w    = tid >> 5, lane = tid & 31;
    __shared__ int   s_bufc[4][128];
    __shared__ int   s_cnt[4];
    __shared__ float s_diag;

    const float4* arow4 = (const float4*)(adj + (size_t)row * N_NODES);
    const int NQ = N_NODES / 4;
    int q0 = w * SEGQ;
    int q1 = min(q0 + SEGQ, NQ);

    int cnt = 0;
    for (int base = q0; base < q1; base += 32) {
        int q = base + lane;
        bool valid = q < q1;
        float a[4] = {0.f, 0.f, 0.f, 0.f};
        int j0 = q * 4;
        if (valid) {
            float4 v = arow4[q];
            a[0] = v.x; a[1] = v.y; a[2] = v.z; a[3] = v.w;
            if (row >= j0 && row < j0 + 4) {
                a[row - j0] += 1.f;
                s_diag = a[row - j0];
            }
        }
#pragma unroll
        for (int t = 0; t < 4; t++) {
            bool has = valid && (a[t] > 0.f);
            unsigned msk = __ballot_sync(0xffffffffu, has);
            if (has) {
                int pos = cnt + __popc(msk & ((1u << lane) - 1u));
                if (pos < 128) s_bufc[w][pos] = j0 + t;
            }
            cnt += __popc(msk);
        }
    }
    if (lane == 0) s_cnt[w] = cnt;
    __syncthreads();

    int c0 = 0;
#pragma unroll
    for (int t = 0; t < 4; t++) if (t < w) c0 += s_cnt[t];
    int myc = min(s_cnt[w], 128);
    for (int k = lane; k < myc; k += 32) {
        int pos = c0 + k;
        if (pos < MAXDEG) g_cols[row * MAXDEG + pos] = s_bufc[w][k];
    }
    if (tid == 0) {
        int tot = s_cnt[0] + s_cnt[1] + s_cnt[2] + s_cnt[3];
        float dsc = s_diag;
        g_cnt[row]  = tot < MAXDEG ? tot : MAXDEG;
        g_dinv[row] = rsqrtf((float)tot + dsc - 1.f);
        g_dsc[row]  = dsc;
    }
}

// ---------------- 4. layer-1 attention: HFMA2 gather (R14 best config) -------
__global__ __launch_bounds__(256) void attn1() {
    int i = blockIdx.x;
    int tid = threadIdx.x;
    int head = tid >> 5, lane = tid & 31;
    __shared__ int   s_cols[MAXDEG];            // byte offsets: j * CAT * 2
    __shared__ float s_w[MAXDEG];
    __shared__ float s_p[HEADS][PDEG];          // e-values -> probs -> half2 coef bits
    __shared__ float s_si[HEADS];
    int n = g_cnt[i];
    int n8 = (n + 7) & ~7;
    float di = g_dinv[i];
    float dsc = g_dsc[i];
    for (int k = tid; k < n8; k += 256) {
        if (k < n) {
            int j = g_cols[i * MAXDEG + k];
            s_cols[k] = j << 10;                // j * 1024 bytes
            float wv = di * g_dinv[j];
            s_w[k] = (j == i) ? wv * dsc : wv;
        } else {
            s_cols[k] = 0;
        }
    }
    if (tid < HEADS) s_si[tid] = g_srcT[i * HEADS + tid];
    __syncthreads();

    // phase 1: cooperative e-matrix; lane = (edge, head) -> coalesced dstT
    {
        int eh_e = tid >> 3, eh_h = tid & 7;
        float si_h = s_si[eh_h];
        for (int k = eh_e; k < n; k += 32) {
            float dst = __ldg(g_dstT + (s_cols[k] >> 7) + eh_h);   // j*8 + h
            s_p[eh_h][k] = lrelu(si_h + dst);
        }
    }
    __syncthreads();

    // phase 2: per-head softmax; finalize coef as packed half2
    float m = -1e30f;
    for (int k = lane; k < n; k += 32) m = fmaxf(m, s_p[head][k]);
#pragma unroll
    for (int o = 16; o; o >>= 1) m = fmaxf(m, __shfl_xor_sync(0xffffffffu, m, o));
    float s = 0.f;
    for (int k = lane; k < n; k += 32) {
        float p = __expf(s_p[head][k] - m);
        s_p[head][k] = p;
        s += p;
    }
#pragma unroll
    for (int o = 16; o; o >>= 1) s += __shfl_xor_sync(0xffffffffu, s, o);
    float inv = 1.f / s;
    for (int k = lane; k < n8; k += 32) {
        float c = (k < n) ? s_p[head][k] * inv * s_w[k] : 0.f;
        __half2 c2 = __float2half2_rn(c);
        s_p[head][k] = __uint_as_float(*(uint32_t*)&c2);
    }
    __syncwarp();

    // phase 3: HFMA2 gather; lane = (e,f); 4 edges/iter, promote every 8 edges
    int e = lane >> 3, f = lane & 7;
    const char* Hbase = (const char*)(g_Hh + head * HID + f * 8);
    float accf[8] = {};
    const __half2 z2 = __float2half2_rn(0.f);
    __half2 ha0 = z2, ha1 = z2, ha2 = z2, ha3 = z2;
    for (int k = 0; k < n8; k += 8) {
#pragma unroll
        for (int su = 0; su < 2; su++) {
            int edge = k + su * 4 + e;
            uint32_t cb = __float_as_uint(s_p[head][edge]);
            __half2 c2 = *reinterpret_cast<__half2*>(&cb);
            uint4 raw = *(const uint4*)(Hbase + s_cols[edge]);
            const __half2* hx = (const __half2*)&raw;
            ha0 = __hfma2(c2, hx[0], ha0);
            ha1 = __hfma2(c2, hx[1], ha1);
            ha2 = __hfma2(c2, hx[2], ha2);
            ha3 = __hfma2(c2, hx[3], ha3);
        }
        float2 f0 = __half22float2(ha0), f1 = __half22float2(ha1);
        float2 f2 = __half22float2(ha2), f3 = __half22float2(ha3);
        accf[0] += f0.x; accf[1] += f0.y; accf[2] += f1.x; accf[3] += f1.y;
        accf[4] += f2.x; accf[5] += f2.y; accf[6] += f3.x; accf[7] += f3.y;
        ha0 = z2; ha1 = z2; ha2 = z2; ha3 = z2;
    }
#pragma unroll
    for (int t = 0; t < 8; t++) {
        accf[t] += __shfl_xor_sync(0xffffffffu, accf[t], 8);
        accf[t] += __shfl_xor_sync(0xffffffffu, accf[t], 16);
    }
    if (e == 0) {
        float4 o0 = make_float4(elu1(accf[0]), elu1(accf[1]), elu1(accf[2]), elu1(accf[3]));
        float4 o1 = make_float4(elu1(accf[4]), elu1(accf[5]), elu1(accf[6]), elu1(accf[7]));
        float* dst = g_X1 + (size_t)i * CAT + head * HID + f * 8;
        *(float4*)(dst)     = o0;
        *(float4*)(dst + 4) = o1;
    }
}

// ---------------- 5. H2 + src2/dst2: 4 rows/block, W_out in smem -------------
__global__ __launch_bounds__(256) void h2_srcdst(const float* __restrict__ W_out,
                                                 const float* __restrict__ a_out) {
    int i0 = blockIdx.x * 4;
    int tid = threadIdx.x;
    __shared__ float sW[IN_DIM * NCLASS];      // 32KB
    __shared__ float sx[4][IN_DIM];            // 8KB
    __shared__ float sp[4][2][NCLASS];
    __shared__ float sh[4][NCLASS];
#pragma unroll
    for (int q = 0; q < 8; q++)
        *(float4*)&sW[tid * 4 + q * 1024] = *(const float4*)(W_out + tid * 4 + q * 1024);
#pragma unroll
    for (int q = 0; q < 2; q++) {
        int idx = tid * 4 + q * 1024;
        *(float4*)&sx[idx >> 9][idx & 511] = *(const float4*)(g_X1 + (size_t)i0 * IN_DIM + idx);
    }
    __syncthreads();

    int warp = tid >> 5, lane = tid & 31;
    int r = warp >> 1, half = warp & 1;
    int c = lane & 15, sub = lane >> 4;
    float p = 0.f;
    int kbase = half * 256;
#pragma unroll 8
    for (int kk = 0; kk < 128; kk++) {
        int k = kbase + kk * 2 + sub;
        p = fmaf(sx[r][k], sW[k * NCLASS + c], p);
    }
    p += __shfl_xor_sync(0xffffffffu, p, 16);
    if (sub == 0) sp[r][half][c] = p;
    __syncthreads();
    if (tid < 64) {
        int rr = tid >> 4, cc = tid & 15;
        float v = sp[rr][0][cc] + sp[rr][1][cc];
        g_H2[(i0 + rr) * NCLASS + cc] = v;
        sh[rr][cc] = v;
    }
    __syncthreads();
    if (tid < 8) {
        int rr = tid >> 1, which = tid & 1;
        const float* a = a_out + which * NCLASS;
        float v = 0.f;
#pragma unroll
        for (int cc = 0; cc < NCLASS; cc++) v = fmaf(sh[rr][cc], __ldg(a + cc), v);
        if (which == 0) g_s2[i0 + rr] = v;
        else            g_d2[i0 + rr] = v;
    }
}

// ---------------- 6. fused layer-2 attention + FC head + log_softmax ---------
__global__ void attn2_head(const float* __restrict__ FC1,
                           const float* __restrict__ FC2,
                           float* __restrict__ out) {
    int w = threadIdx.x >> 5, lane = threadIdx.x & 31;
    int i = blockIdx.x * 4 + w;
    __shared__ int   s_c[4][MAXDEG];
    __shared__ float s_w[4][MAXDEG];
    __shared__ float s_p[4][MAXDEG];
    if (i >= N_NODES) return;
    int n = g_cnt[i];
    float si = g_s2[i];
    float di = g_dinv[i];
    float dsc = g_dsc[i];
    float m = -1e30f;
    for (int k = lane; k < n; k += 32) {
        int j = g_cols[i * MAXDEG + k];
        s_c[w][k] = j;
        float wv = di * g_dinv[j];
        s_w[w][k] = (j == i) ? wv * dsc : wv;
        float e = lrelu(si + g_d2[j]);
        s_p[w][k] = e;
        m = fmaxf(m, e);
    }
#pragma unroll
    for (int o = 16; o; o >>= 1) m = fmaxf(m, __shfl_xor_sync(0xffffffffu, m, o));
    float s = 0.f;
    for (int k = lane; k < n; k += 32) {
        float p = __expf(s_p[w][k] - m);
        s_p[w][k] = p;
        s += p;
    }
#pragma unroll
    for (int o = 16; o; o >>= 1) s += __shfl_xor_sync(0xffffffffu, s, o);
    float inv = 1.f / s;
    __syncwarp();
    float z = 0.f;
    if (lane < NCLASS) {
        float acc = 0.f;
        for (int k = 0; k < n; k++) {
            float coef = s_p[w][k] * inv * s_w[w][k];
            acc = fmaf(coef, g_H2[s_c[w][k] * NCLASS + lane], acc);
        }
        z = elu1(elu1(acc));
    }
    // FC head (warp-level, z on lanes 0..15)
    float y1 = 0.f;
#pragma unroll
    for (int k = 0; k < NCLASS; k++) {
        float zk = __shfl_sync(0xffffffffu, z, k);
        if (lane < NCLASS) y1 = fmaf(zk, __ldg(FC1 + lane * NCLASS + k), y1);
    }
    y1 = elu1(y1);
    float y2 = 0.f;
#pragma unroll
    for (int k = 0; k < NCLASS; k++) {
        float yk = __shfl_sync(0xffffffffu, y1, k);
        if (lane < NCLASS) y2 = fmaf(yk, __ldg(FC2 + lane * NCLASS + k), y2);
    }
    y2 = elu1(y2);
    float v = (lane < NCLASS) ? y2 : -1e30f;
#pragma unroll
    for (int o = 8; o; o >>= 1) v = fmaxf(v, __shfl_xor_sync(0xffffffffu, v, o));
    float e = (lane < NCLASS) ? expf(y2 - v) : 0.f;
    float sum = e;
#pragma unroll
    for (int o = 8; o; o >>= 1) sum += __shfl_xor_sync(0xffffffffu, sum, o);
    if (lane < NCLASS) out[i * NCLASS + lane] = y2 - v - logf(sum);
}

// ---------------- launcher ---------------------------------------------------
extern "C" void kernel_launch(void* const* d_in, const int* in_sizes, int n_in,
                              void* d_out, int out_size) {
    const float* adj     = (const float*)d_in[0];
    const float* feat    = (const float*)d_in[1];
    const float* W_heads = (const float*)d_in[2];
    const float* a_heads = (const float*)d_in[3];
    const float* W_out   = (const float*)d_in[4];
    const float* a_out   = (const float*)d_in[5];
    const float* FC1     = (const float*)d_in[6];
    const float* FC2     = (const float*)d_in[7];
    float* out = (float*)d_out;

    prep_all   <<<HEADS * NCHUNK + N_NODES, 256>>>(W_heads, feat);       // 1
    sgemm_tc   <<<dim3(HEADS, (N_NODES + 63) / 64), 128>>>(a_heads);     // 2
    build_edges<<<N_NODES, 128>>>(adj);                                  // 3
    attn1      <<<N_NODES, 256>>>();                                     // 4 (profiled)
    h2_srcdst  <<<N_NODES / 4, 256>>>(W_out, a_out);                     // 5
    attn2_head <<<(N_NODES + 3) / 4, 128>>>(FC1, FC2, out);              // 6
}